// round 1
// baseline (speedup 1.0000x reference)
#include <cuda_runtime.h>
#include <math.h>

#define BATCH 16
#define C 512
#define HW 1024
#define NGROUP 32
#define CPG 16
#define GSIZE (CPG*HW)          // 16384 contiguous floats per (b,group)
#define QK_SCALE 0.04419417382415922f  // 1/sqrt(512)

#define KT 16
#define BT 64
#define SPAD 68                 // padded smem row stride (floats), 16B-aligned rows

// -------- scratch (static device globals; no runtime allocation) --------
__device__ float g_x[BATCH*C*HW];   // normalized input   (32 MB)
__device__ float g_q[BATCH*C*HW];   // Q                  (32 MB)
__device__ float g_k[BATCH*C*HW];   // K                  (32 MB)
__device__ float g_v[BATCH*C*HW];   // V                  (32 MB)
__device__ float g_s[BATCH*HW*HW];  // attn logits/probs  (64 MB)
__device__ float g_a[BATCH*C*HW];   // attention output   (32 MB)

// ============================ GroupNorm ============================
// One block per (batch, group). Each group = 16 channels * 1024 px, contiguous.
__global__ __launch_bounds__(256) void gn_kernel(const float* __restrict__ inp,
                                                 const float* __restrict__ gamma,
                                                 const float* __restrict__ beta) {
    int bg = blockIdx.x;               // 0..BATCH*NGROUP-1
    int g  = bg % NGROUP;
    const float4* src = (const float4*)(inp + (size_t)bg * GSIZE);
    float4*       dst = (float4*)(g_x + (size_t)bg * GSIZE);

    float s = 0.f, ss = 0.f;
    #pragma unroll 4
    for (int i = threadIdx.x; i < GSIZE/4; i += 256) {
        float4 v = src[i];
        s  += v.x + v.y + v.z + v.w;
        ss += v.x*v.x + v.y*v.y + v.z*v.z + v.w*v.w;
    }
    __shared__ float sh1[8], sh2[8];
    #pragma unroll
    for (int o = 16; o > 0; o >>= 1) {
        s  += __shfl_down_sync(0xffffffffu, s,  o);
        ss += __shfl_down_sync(0xffffffffu, ss, o);
    }
    int lane = threadIdx.x & 31, wid = threadIdx.x >> 5;
    if (lane == 0) { sh1[wid] = s; sh2[wid] = ss; }
    __syncthreads();
    if (threadIdx.x == 0) {
        float t1 = 0.f, t2 = 0.f;
        #pragma unroll
        for (int i = 0; i < 8; i++) { t1 += sh1[i]; t2 += sh2[i]; }
        sh1[0] = t1; sh2[0] = t2;
    }
    __syncthreads();
    float mu   = sh1[0] * (1.f/GSIZE);
    float var  = sh2[0] * (1.f/GSIZE) - mu*mu;
    float rstd = rsqrtf(var + 1e-6f);

    #pragma unroll 4
    for (int i = threadIdx.x; i < GSIZE/4; i += 256) {
        int c = g*CPG + (i >> 8);      // 256 float4 per channel
        float ga = gamma[c] * rstd, be = beta[c];
        float4 v = src[i];
        v.x = (v.x - mu)*ga + be;
        v.y = (v.y - mu)*ga + be;
        v.z = (v.z - mu)*ga + be;
        v.w = (v.w - mu)*ga + be;
        dst[i] = v;
    }
}

// ============================ fused QKV GEMM ============================
// Q/K/V[b,o,n] = sum_c W[o,c] * x[b,c,n] + bias[o].
// 64x64 tile, KT=16, 256 threads, 4x4 microtile; x tile shared by 3 weights.
__global__ __launch_bounds__(256) void qkv_kernel(const float* __restrict__ Wq, const float* __restrict__ bq,
                                                  const float* __restrict__ Wk, const float* __restrict__ bk,
                                                  const float* __restrict__ Wv, const float* __restrict__ bv) {
    __shared__ float Aq[KT][SPAD], Ak[KT][SPAD], Av[KT][SPAD], Bs[KT][SPAD];
    int b  = blockIdx.z;
    int n0 = blockIdx.x * BT;
    int o0 = blockIdx.y * BT;
    int t  = threadIdx.x;
    int tx = t & 15, ty = t >> 4;
    int lk = t & 15, lr = t >> 4;       // weight loads: 16 consecutive c per o-row
    int bcol = t & 63, brow = t >> 6;   // x loads: 64 consecutive n per c-row
    const float* xb = g_x + (size_t)b*C*HW;

    float acc[3][4][4] = {};

    for (int k0 = 0; k0 < C; k0 += KT) {
        #pragma unroll
        for (int p = 0; p < 4; p++) {
            int r  = lr + p*16;
            int gi = (o0 + r)*C + k0 + lk;
            Aq[lk][r] = Wq[gi];
            Ak[lk][r] = Wk[gi];
            Av[lk][r] = Wv[gi];
        }
        #pragma unroll
        for (int p = 0; p < 4; p++) {
            int kk = brow + p*4;
            Bs[kk][bcol] = xb[(size_t)(k0+kk)*HW + n0 + bcol];
        }
        __syncthreads();
        #pragma unroll
        for (int k = 0; k < KT; k++) {
            float4 xv = *(const float4*)&Bs[k][tx*4];
            float4 q4 = *(const float4*)&Aq[k][ty*4];
            float4 k4 = *(const float4*)&Ak[k][ty*4];
            float4 v4 = *(const float4*)&Av[k][ty*4];
            float xs[4] = {xv.x, xv.y, xv.z, xv.w};
            float qs[4] = {q4.x, q4.y, q4.z, q4.w};
            float ks[4] = {k4.x, k4.y, k4.z, k4.w};
            float vs[4] = {v4.x, v4.y, v4.z, v4.w};
            #pragma unroll
            for (int i = 0; i < 4; i++)
                #pragma unroll
                for (int j = 0; j < 4; j++) {
                    acc[0][i][j] += qs[i]*xs[j];
                    acc[1][i][j] += ks[i]*xs[j];
                    acc[2][i][j] += vs[i]*xs[j];
                }
        }
        __syncthreads();
    }

    size_t base = (size_t)b*C*HW;
    #pragma unroll
    for (int i = 0; i < 4; i++) {
        int row = o0 + ty*4 + i;
        size_t off = base + (size_t)row*HW + n0 + tx*4;
        float vq = bq[row], vk = bk[row], vv = bv[row];
        float4 oq = {acc[0][i][0]+vq, acc[0][i][1]+vq, acc[0][i][2]+vq, acc[0][i][3]+vq};
        float4 ok = {acc[1][i][0]+vk, acc[1][i][1]+vk, acc[1][i][2]+vk, acc[1][i][3]+vk};
        float4 ov = {acc[2][i][0]+vv, acc[2][i][1]+vv, acc[2][i][2]+vv, acc[2][i][3]+vv};
        *(float4*)&g_q[off] = oq;
        *(float4*)&g_k[off] = ok;
        *(float4*)&g_v[off] = ov;
    }
}

// ============================ S = Q^T K * scale ============================
// S[b,n,m] = sum_c Q[b,c,n]*K[b,c,m] * QK_SCALE. Both operands n/m-contiguous.
__global__ __launch_bounds__(256) void s_kernel() {
    __shared__ float As[KT][SPAD], Bs[KT][SPAD];
    int b  = blockIdx.z;
    int m0 = blockIdx.x * BT;
    int n0 = blockIdx.y * BT;
    int t  = threadIdx.x;
    int tx = t & 15, ty = t >> 4;
    int col = t & 63, krow = t >> 6;
    const float* Qb = g_q + (size_t)b*C*HW;
    const float* Kb = g_k + (size_t)b*C*HW;

    float acc[4][4] = {};

    for (int k0 = 0; k0 < C; k0 += KT) {
        #pragma unroll
        for (int p = 0; p < 4; p++) {
            int kk = krow + p*4;
            As[kk][col] = Qb[(size_t)(k0+kk)*HW + n0 + col];
            Bs[kk][col] = Kb[(size_t)(k0+kk)*HW + m0 + col];
        }
        __syncthreads();
        #pragma unroll
        for (int k = 0; k < KT; k++) {
            float4 a4 = *(const float4*)&As[k][ty*4];
            float4 b4 = *(const float4*)&Bs[k][tx*4];
            float as[4] = {a4.x,a4.y,a4.z,a4.w};
            float bs[4] = {b4.x,b4.y,b4.z,b4.w};
            #pragma unroll
            for (int i = 0; i < 4; i++)
                #pragma unroll
                for (int j = 0; j < 4; j++)
                    acc[i][j] += as[i]*bs[j];
        }
        __syncthreads();
    }

    float* Sb = g_s + (size_t)b*HW*HW;
    #pragma unroll
    for (int i = 0; i < 4; i++) {
        int row = n0 + ty*4 + i;
        float4 o = {acc[i][0]*QK_SCALE, acc[i][1]*QK_SCALE, acc[i][2]*QK_SCALE, acc[i][3]*QK_SCALE};
        *(float4*)&Sb[(size_t)row*HW + m0 + tx*4] = o;
    }
}

// ============================ row softmax over m ============================
__global__ __launch_bounds__(256) void softmax_kernel() {
    size_t row = blockIdx.x;            // b*HW + n
    float4* p = (float4*)(g_s + row*(size_t)HW);
    float4 v = p[threadIdx.x];

    __shared__ float sh[8];
    int lane = threadIdx.x & 31, wid = threadIdx.x >> 5;

    float m = fmaxf(fmaxf(v.x, v.y), fmaxf(v.z, v.w));
    #pragma unroll
    for (int o = 16; o > 0; o >>= 1) m = fmaxf(m, __shfl_xor_sync(0xffffffffu, m, o));
    if (lane == 0) sh[wid] = m;
    __syncthreads();
    m = sh[0];
    #pragma unroll
    for (int i = 1; i < 8; i++) m = fmaxf(m, sh[i]);
    __syncthreads();

    float4 e;
    e.x = expf(v.x - m); e.y = expf(v.y - m);
    e.z = expf(v.z - m); e.w = expf(v.w - m);
    float s = e.x + e.y + e.z + e.w;
    #pragma unroll
    for (int o = 16; o > 0; o >>= 1) s += __shfl_xor_sync(0xffffffffu, s, o);
    if (lane == 0) sh[wid] = s;
    __syncthreads();
    s = sh[0];
    #pragma unroll
    for (int i = 1; i < 8; i++) s += sh[i];
    float r = 1.f / s;
    e.x *= r; e.y *= r; e.z *= r; e.w *= r;
    p[threadIdx.x] = e;
}

// ============================ A = V @ attn^T ============================
// A[b,c,n] = sum_m V[b,c,m] * attn[b,n,m]. K-dim (m) contiguous in both.
__global__ __launch_bounds__(256) void av_kernel() {
    __shared__ float As[KT][SPAD], Bs[KT][SPAD];
    int b  = blockIdx.z;
    int n0 = blockIdx.x * BT;
    int c0 = blockIdx.y * BT;
    int t  = threadIdx.x;
    int tx = t & 15, ty = t >> 4;
    int lk = t & 15, lr = t >> 4;
    const float* Vb = g_v + (size_t)b*C*HW;
    const float* Sb = g_s + (size_t)b*HW*HW;

    float acc[4][4] = {};

    for (int m0 = 0; m0 < HW; m0 += KT) {
        #pragma unroll
        for (int p = 0; p < 4; p++) {
            int r = lr + p*16;
            As[lk][r] = Vb[(size_t)(c0+r)*HW + m0 + lk];    // A[k][c-row]
            Bs[lk][r] = Sb[(size_t)(n0+r)*HW + m0 + lk];    // B[k][n-col] = attn[n,m]
        }
        __syncthreads();
        #pragma unroll
        for (int k = 0; k < KT; k++) {
            float4 a4 = *(const float4*)&As[k][ty*4];
            float4 b4 = *(const float4*)&Bs[k][tx*4];
            float as[4] = {a4.x,a4.y,a4.z,a4.w};
            float bs[4] = {b4.x,b4.y,b4.z,b4.w};
            #pragma unroll
            for (int i = 0; i < 4; i++)
                #pragma unroll
                for (int j = 0; j < 4; j++)
                    acc[i][j] += as[i]*bs[j];
        }
        __syncthreads();
    }

    size_t base = (size_t)b*C*HW;
    #pragma unroll
    for (int i = 0; i < 4; i++) {
        int row = c0 + ty*4 + i;
        float4 o = {acc[i][0], acc[i][1], acc[i][2], acc[i][3]};
        *(float4*)&g_a[base + (size_t)row*HW + n0 + tx*4] = o;
    }
}

// ============================ out = Wo @ A + bo + inp ============================
__global__ __launch_bounds__(256) void out_kernel(const float* __restrict__ Wo, const float* __restrict__ bo,
                                                  const float* __restrict__ inp, float* __restrict__ out) {
    __shared__ float As[KT][SPAD], Bs[KT][SPAD];
    int b  = blockIdx.z;
    int n0 = blockIdx.x * BT;
    int o0 = blockIdx.y * BT;
    int t  = threadIdx.x;
    int tx = t & 15, ty = t >> 4;
    int lk = t & 15, lr = t >> 4;
    int bcol = t & 63, brow = t >> 6;
    const float* ab = g_a + (size_t)b*C*HW;

    float acc[4][4] = {};

    for (int k0 = 0; k0 < C; k0 += KT) {
        #pragma unroll
        for (int p = 0; p < 4; p++) {
            int r = lr + p*16;
            As[lk][r] = Wo[(o0 + r)*C + k0 + lk];
        }
        #pragma unroll
        for (int p = 0; p < 4; p++) {
            int kk = brow + p*4;
            Bs[kk][bcol] = ab[(size_t)(k0+kk)*HW + n0 + bcol];
        }
        __syncthreads();
        #pragma unroll
        for (int k = 0; k < KT; k++) {
            float4 a4 = *(const float4*)&As[k][ty*4];
            float4 b4 = *(const float4*)&Bs[k][tx*4];
            float as[4] = {a4.x,a4.y,a4.z,a4.w};
            float bs[4] = {b4.x,b4.y,b4.z,b4.w};
            #pragma unroll
            for (int i = 0; i < 4; i++)
                #pragma unroll
                for (int j = 0; j < 4; j++)
                    acc[i][j] += as[i]*bs[j];
        }
        __syncthreads();
    }

    size_t base = (size_t)b*C*HW;
    #pragma unroll
    for (int i = 0; i < 4; i++) {
        int row = o0 + ty*4 + i;
        size_t off = base + (size_t)row*HW + n0 + tx*4;
        float bias = bo[row];
        float4 r = *(const float4*)&inp[off];
        float4 o = {acc[i][0]+bias+r.x, acc[i][1]+bias+r.y, acc[i][2]+bias+r.z, acc[i][3]+bias+r.w};
        *(float4*)&out[off] = o;
    }
}

// ============================ launch ============================
extern "C" void kernel_launch(void* const* d_in, const int* in_sizes, int n_in,
                              void* d_out, int out_size) {
    const float* inp   = (const float*)d_in[0];
    const float* gamma = (const float*)d_in[1];
    const float* beta  = (const float*)d_in[2];
    const float* Wq    = (const float*)d_in[3];
    const float* bq    = (const float*)d_in[4];
    const float* Wk    = (const float*)d_in[5];
    const float* bk    = (const float*)d_in[6];
    const float* Wv    = (const float*)d_in[7];
    const float* bv    = (const float*)d_in[8];
    const float* Wo    = (const float*)d_in[9];
    const float* bo    = (const float*)d_in[10];
    float* out = (float*)d_out;

    gn_kernel<<<BATCH*NGROUP, 256>>>(inp, gamma, beta);
    qkv_kernel<<<dim3(HW/BT, C/BT, BATCH), 256>>>(Wq, bq, Wk, bk, Wv, bv);
    s_kernel<<<dim3(HW/BT, HW/BT, BATCH), 256>>>();
    softmax_kernel<<<BATCH*HW, 256>>>();
    av_kernel<<<dim3(HW/BT, C/BT, BATCH), 256>>>();
    out_kernel<<<dim3(HW/BT, C/BT, BATCH), 256>>>(Wo, bo, inp, out);
}

// round 2
// speedup vs baseline: 2.2147x; 2.2147x over previous
#include <cuda_runtime.h>
#include <math.h>

#define BATCH 16
#define C 512
#define HW 1024
#define NGROUP 32
#define CPG 16
#define GSIZE (CPG*HW)
#define QK_SCALE 0.04419417382415922f  // 1/sqrt(512)

// -------- scratch (static device globals; no runtime allocation) --------
__device__ float g_x[BATCH*C*HW];
__device__ float g_q[BATCH*C*HW];
__device__ float g_k[BATCH*C*HW];
__device__ float g_v[BATCH*C*HW];
__device__ float g_s[BATCH*HW*HW];
__device__ float g_a[BATCH*C*HW];

// ============================ GroupNorm ============================
__global__ __launch_bounds__(256) void gn_kernel(const float* __restrict__ inp,
                                                 const float* __restrict__ gamma,
                                                 const float* __restrict__ beta) {
    int bg = blockIdx.x;
    int g  = bg % NGROUP;
    const float4* src = (const float4*)(inp + (size_t)bg * GSIZE);
    float4*       dst = (float4*)(g_x + (size_t)bg * GSIZE);

    float s = 0.f, ss = 0.f;
    #pragma unroll 4
    for (int i = threadIdx.x; i < GSIZE/4; i += 256) {
        float4 v = src[i];
        s  += v.x + v.y + v.z + v.w;
        ss += v.x*v.x + v.y*v.y + v.z*v.z + v.w*v.w;
    }
    __shared__ float sh1[8], sh2[8];
    #pragma unroll
    for (int o = 16; o > 0; o >>= 1) {
        s  += __shfl_down_sync(0xffffffffu, s,  o);
        ss += __shfl_down_sync(0xffffffffu, ss, o);
    }
    int lane = threadIdx.x & 31, wid = threadIdx.x >> 5;
    if (lane == 0) { sh1[wid] = s; sh2[wid] = ss; }
    __syncthreads();
    if (threadIdx.x == 0) {
        float t1 = 0.f, t2 = 0.f;
        #pragma unroll
        for (int i = 0; i < 8; i++) { t1 += sh1[i]; t2 += sh2[i]; }
        sh1[0] = t1; sh2[0] = t2;
    }
    __syncthreads();
    float mu   = sh1[0] * (1.f/GSIZE);
    float var  = sh2[0] * (1.f/GSIZE) - mu*mu;
    float rstd = rsqrtf(var + 1e-6f);

    #pragma unroll 4
    for (int i = threadIdx.x; i < GSIZE/4; i += 256) {
        int c = g*CPG + (i >> 8);
        float ga = gamma[c] * rstd, be = beta[c];
        float4 v = src[i];
        v.x = (v.x - mu)*ga + be;
        v.y = (v.y - mu)*ga + be;
        v.z = (v.z - mu)*ga + be;
        v.w = (v.w - mu)*ga + be;
        dst[i] = v;
    }
}

// ============================ row softmax over m ============================
__global__ __launch_bounds__(256) void softmax_kernel() {
    size_t row = blockIdx.x;            // b*HW + n
    float4* p = (float4*)(g_s + row*(size_t)HW);
    float4 v = p[threadIdx.x];

    __shared__ float sh[8];
    int lane = threadIdx.x & 31, wid = threadIdx.x >> 5;

    float m = fmaxf(fmaxf(v.x, v.y), fmaxf(v.z, v.w));
    #pragma unroll
    for (int o = 16; o > 0; o >>= 1) m = fmaxf(m, __shfl_xor_sync(0xffffffffu, m, o));
    if (lane == 0) sh[wid] = m;
    __syncthreads();
    m = sh[0];
    #pragma unroll
    for (int i = 1; i < 8; i++) m = fmaxf(m, sh[i]);
    __syncthreads();

    float4 e;
    e.x = __expf(v.x - m); e.y = __expf(v.y - m);
    e.z = __expf(v.z - m); e.w = __expf(v.w - m);
    float s = e.x + e.y + e.z + e.w;
    #pragma unroll
    for (int o = 16; o > 0; o >>= 1) s += __shfl_xor_sync(0xffffffffu, s, o);
    if (lane == 0) sh[wid] = s;
    __syncthreads();
    s = sh[0];
    #pragma unroll
    for (int i = 1; i < 8; i++) s += sh[i];
    float r = 1.f / s;
    e.x *= r; e.y *= r; e.z *= r; e.w *= r;
    p[threadIdx.x] = e;
}

// ============================ tf32 tensor-core GEMM ============================
// C[b][m][n] = sum_k Aop[k][m] * Bop[k][n]  (+bias[m]) (*scale) (+res)
// AKM: A stored A[k*lda + m] else A[m*lda + k]
// BKN: B stored B[k*ldb + n] else B[n*ldb + k]
// Block tile 128x128x32, 8 warps (4 along M x 2 along N), warp tile 32x64.
// smem layout: word index = k*128 + (col ^ f(k)); f makes both scatter stores
// and fragment loads bank-conflict-free.

__device__ __forceinline__ unsigned f2tf(float x) {
    unsigned r; asm("cvt.rna.tf32.f32 %0, %1;" : "=r"(r) : "f"(x)); return r;
}
__device__ __forceinline__ int fkx(int k) {
    return ((k & 3) << 3) ^ (((k >> 2) & 7) << 2);
}

template<bool AKM, bool BKN, bool BIAS, bool RES, bool SCALE>
__global__ __launch_bounds__(256, 2) void mm_tf32(
    const float* __restrict__ Ag, const float* __restrict__ Bg,
    float* __restrict__ Cg, const float* __restrict__ bias,
    const float* __restrict__ resg,
    int N, int K, int lda, int ldb,
    long sA, long sB, long sC)
{
    __shared__ unsigned As[32*128], Bs[32*128];
    const int t = threadIdx.x, lane = t & 31, w = t >> 5;
    const int m0 = blockIdx.y * 128, n0 = blockIdx.x * 128, b = blockIdx.z;
    const float* A = Ag + (size_t)b * sA;
    const float* B = Bg + (size_t)b * sB;
    float* Cb = Cg + (size_t)b * sC;

    const int wm = (w & 3) * 32, wn = (w >> 2) * 64;
    float acc[2][8][4];
    #pragma unroll
    for (int i = 0; i < 2; i++)
        #pragma unroll
        for (int j = 0; j < 8; j++)
            #pragma unroll
            for (int r = 0; r < 4; r++) acc[i][j][r] = 0.f;

    for (int k0 = 0; k0 < K; k0 += 32) {
        // ---- stage A tile (32k x 128m) ----
        if (AKM) {
            int kk = t >> 5, m4 = (t & 31) * 4;
            #pragma unroll
            for (int p = 0; p < 4; p++) {
                int k = kk + p * 8;
                float4 v = *(const float4*)(A + (size_t)(k0 + k) * lda + m0 + m4);
                uint4 u = {f2tf(v.x), f2tf(v.y), f2tf(v.z), f2tf(v.w)};
                *(uint4*)&As[k * 128 + (m4 ^ fkx(k))] = u;
            }
        } else {
            int mr = t >> 3, kq = (t & 7) * 4;
            #pragma unroll
            for (int p = 0; p < 4; p++) {
                int m = mr + p * 32;
                float4 v = *(const float4*)(A + (size_t)(m0 + m) * lda + k0 + kq);
                As[(kq + 0) * 128 + (m ^ fkx(kq + 0))] = f2tf(v.x);
                As[(kq + 1) * 128 + (m ^ fkx(kq + 1))] = f2tf(v.y);
                As[(kq + 2) * 128 + (m ^ fkx(kq + 2))] = f2tf(v.z);
                As[(kq + 3) * 128 + (m ^ fkx(kq + 3))] = f2tf(v.w);
            }
        }
        // ---- stage B tile (32k x 128n) ----
        if (BKN) {
            int kk = t >> 5, n4 = (t & 31) * 4;
            #pragma unroll
            for (int p = 0; p < 4; p++) {
                int k = kk + p * 8;
                float4 v = *(const float4*)(B + (size_t)(k0 + k) * ldb + n0 + n4);
                uint4 u = {f2tf(v.x), f2tf(v.y), f2tf(v.z), f2tf(v.w)};
                *(uint4*)&Bs[k * 128 + (n4 ^ fkx(k))] = u;
            }
        } else {
            int nr = t >> 3, kq = (t & 7) * 4;
            #pragma unroll
            for (int p = 0; p < 4; p++) {
                int n = nr + p * 32;
                float4 v = *(const float4*)(B + (size_t)(n0 + n) * ldb + k0 + kq);
                Bs[(kq + 0) * 128 + (n ^ fkx(kq + 0))] = f2tf(v.x);
                Bs[(kq + 1) * 128 + (n ^ fkx(kq + 1))] = f2tf(v.y);
                Bs[(kq + 2) * 128 + (n ^ fkx(kq + 2))] = f2tf(v.z);
                Bs[(kq + 3) * 128 + (n ^ fkx(kq + 3))] = f2tf(v.w);
            }
        }
        __syncthreads();

        #pragma unroll
        for (int ks = 0; ks < 4; ks++) {
            const int kb = ks * 8;
            const int kk = lane & 3, gg = lane >> 2;
            const int kA0 = kb + kk, kA1 = kb + kk + 4;
            const int f0 = fkx(kA0), f1 = fkx(kA1);
            unsigned a[2][4];
            #pragma unroll
            for (int mi = 0; mi < 2; mi++) {
                int mr = wm + mi * 16 + gg;
                a[mi][0] = As[kA0 * 128 + (mr ^ f0)];
                a[mi][1] = As[kA0 * 128 + ((mr + 8) ^ f0)];
                a[mi][2] = As[kA1 * 128 + (mr ^ f1)];
                a[mi][3] = As[kA1 * 128 + ((mr + 8) ^ f1)];
            }
            unsigned bb[8][2];
            #pragma unroll
            for (int ni = 0; ni < 8; ni++) {
                int nc = wn + ni * 8 + gg;
                bb[ni][0] = Bs[kA0 * 128 + (nc ^ f0)];
                bb[ni][1] = Bs[kA1 * 128 + (nc ^ f1)];
            }
            #pragma unroll
            for (int mi = 0; mi < 2; mi++)
                #pragma unroll
                for (int ni = 0; ni < 8; ni++)
                    asm volatile(
                        "mma.sync.aligned.m16n8k8.row.col.f32.tf32.tf32.f32 "
                        "{%0,%1,%2,%3}, {%4,%5,%6,%7}, {%8,%9}, {%0,%1,%2,%3};"
                        : "+f"(acc[mi][ni][0]), "+f"(acc[mi][ni][1]),
                          "+f"(acc[mi][ni][2]), "+f"(acc[mi][ni][3])
                        : "r"(a[mi][0]), "r"(a[mi][1]), "r"(a[mi][2]), "r"(a[mi][3]),
                          "r"(bb[ni][0]), "r"(bb[ni][1]));
        }
        __syncthreads();
    }

    // ---- epilogue ----
    #pragma unroll
    for (int mi = 0; mi < 2; mi++) {
        int r0 = m0 + wm + mi * 16 + (lane >> 2);
        float b0v = 0.f, b1v = 0.f;
        if (BIAS) { b0v = bias[r0]; b1v = bias[r0 + 8]; }
        #pragma unroll
        for (int ni = 0; ni < 8; ni++) {
            int cc = n0 + wn + ni * 8 + (lane & 3) * 2;
            float v0 = acc[mi][ni][0], v1 = acc[mi][ni][1];
            float v2 = acc[mi][ni][2], v3 = acc[mi][ni][3];
            if (SCALE) { v0 *= QK_SCALE; v1 *= QK_SCALE; v2 *= QK_SCALE; v3 *= QK_SCALE; }
            v0 += b0v; v1 += b0v; v2 += b1v; v3 += b1v;
            if (RES) {
                float2 ra = *(const float2*)(resg + (size_t)b * sC + (size_t)r0 * N + cc);
                float2 rb = *(const float2*)(resg + (size_t)b * sC + (size_t)(r0 + 8) * N + cc);
                v0 += ra.x; v1 += ra.y; v2 += rb.x; v3 += rb.y;
            }
            float2 o0 = {v0, v1}, o1 = {v2, v3};
            *(float2*)(Cb + (size_t)r0 * N + cc) = o0;
            *(float2*)(Cb + (size_t)(r0 + 8) * N + cc) = o1;
        }
    }
}

// ============================ launch ============================
extern "C" void kernel_launch(void* const* d_in, const int* in_sizes, int n_in,
                              void* d_out, int out_size) {
    const float* inp   = (const float*)d_in[0];
    const float* gamma = (const float*)d_in[1];
    const float* beta  = (const float*)d_in[2];
    const float* Wq    = (const float*)d_in[3];
    const float* bq    = (const float*)d_in[4];
    const float* Wk    = (const float*)d_in[5];
    const float* bk    = (const float*)d_in[6];
    const float* Wv    = (const float*)d_in[7];
    const float* bv    = (const float*)d_in[8];
    const float* Wo    = (const float*)d_in[9];
    const float* bo    = (const float*)d_in[10];
    float* out = (float*)d_out;

    void *px, *pq, *pk, *pv, *ps, *pa;
    cudaGetSymbolAddress(&px, g_x);
    cudaGetSymbolAddress(&pq, g_q);
    cudaGetSymbolAddress(&pk, g_k);
    cudaGetSymbolAddress(&pv, g_v);
    cudaGetSymbolAddress(&ps, g_s);
    cudaGetSymbolAddress(&pa, g_a);

    const long sCH = (long)C * HW;
    const long sHH = (long)HW * HW;

    gn_kernel<<<BATCH*NGROUP, 256>>>(inp, gamma, beta);

    // Q/K/V = W @ x + b   (A = weight (M,K) row-major, B = x (K,N))
    mm_tf32<false, true, true, false, false><<<dim3(HW/128, C/128, BATCH), 256>>>(
        Wq, (const float*)px, (float*)pq, bq, nullptr, HW, C, C, HW, 0, sCH, sCH);
    mm_tf32<false, true, true, false, false><<<dim3(HW/128, C/128, BATCH), 256>>>(
        Wk, (const float*)px, (float*)pk, bk, nullptr, HW, C, C, HW, 0, sCH, sCH);
    mm_tf32<false, true, true, false, false><<<dim3(HW/128, C/128, BATCH), 256>>>(
        Wv, (const float*)px, (float*)pv, bv, nullptr, HW, C, C, HW, 0, sCH, sCH);

    // S[n][m] = scale * sum_c Q[c][n] K[c][m]   (A = Q (K,M), B = K (K,N))
    mm_tf32<true, true, false, false, true><<<dim3(HW/128, HW/128, BATCH), 256>>>(
        (const float*)pq, (const float*)pk, (float*)ps, nullptr, nullptr,
        HW, C, HW, HW, sCH, sCH, sHH);

    softmax_kernel<<<BATCH*HW, 256>>>();

    // A[c][n] = sum_m V[c][m] attn[n][m]   (A = V (M,K), B = attn (N,K))
    mm_tf32<false, false, false, false, false><<<dim3(HW/128, C/128, BATCH), 256>>>(
        (const float*)pv, (const float*)ps, (float*)pa, nullptr, nullptr,
        HW, HW, HW, HW, sCH, sHH, sCH);

    // out = Wo @ A + bo + inp
    mm_tf32<false, true, true, true, false><<<dim3(HW/128, C/128, BATCH), 256>>>(
        Wo, (const float*)pa, out, bo, inp, HW, C, C, HW, 0, sCH, sCH);
}

// round 3
// speedup vs baseline: 2.2151x; 1.0002x over previous
#include <cuda_runtime.h>
#include <math.h>

#define BATCH 16
#define C 512
#define HW 1024
#define NGROUP 32
#define CPG 16
#define GSIZE (CPG*HW)
#define QK_SCALE 0.04419417382415922f  // 1/sqrt(512)

// -------- scratch (static device globals; no runtime allocation) --------
__device__ float g_x[BATCH*C*HW];
__device__ float g_q[BATCH*C*HW];
__device__ float g_k[BATCH*C*HW];
__device__ float g_v[BATCH*C*HW];
__device__ float g_s[BATCH*HW*HW];
__device__ float g_a[BATCH*C*HW];

// ============================ GroupNorm ============================
__global__ __launch_bounds__(256) void gn_kernel(const float* __restrict__ inp,
                                                 const float* __restrict__ gamma,
                                                 const float* __restrict__ beta) {
    int bg = blockIdx.x;
    int g  = bg % NGROUP;
    const float4* src = (const float4*)(inp + (size_t)bg * GSIZE);
    float4*       dst = (float4*)(g_x + (size_t)bg * GSIZE);

    float s = 0.f, ss = 0.f;
    #pragma unroll 4
    for (int i = threadIdx.x; i < GSIZE/4; i += 256) {
        float4 v = src[i];
        s  += v.x + v.y + v.z + v.w;
        ss += v.x*v.x + v.y*v.y + v.z*v.z + v.w*v.w;
    }
    __shared__ float sh1[8], sh2[8];
    #pragma unroll
    for (int o = 16; o > 0; o >>= 1) {
        s  += __shfl_down_sync(0xffffffffu, s,  o);
        ss += __shfl_down_sync(0xffffffffu, ss, o);
    }
    int lane = threadIdx.x & 31, wid = threadIdx.x >> 5;
    if (lane == 0) { sh1[wid] = s; sh2[wid] = ss; }
    __syncthreads();
    if (threadIdx.x == 0) {
        float t1 = 0.f, t2 = 0.f;
        #pragma unroll
        for (int i = 0; i < 8; i++) { t1 += sh1[i]; t2 += sh2[i]; }
        sh1[0] = t1; sh2[0] = t2;
    }
    __syncthreads();
    float mu   = sh1[0] * (1.f/GSIZE);
    float var  = sh2[0] * (1.f/GSIZE) - mu*mu;
    float rstd = rsqrtf(var + 1e-6f);

    #pragma unroll 4
    for (int i = threadIdx.x; i < GSIZE/4; i += 256) {
        int c = g*CPG + (i >> 8);
        float ga = gamma[c] * rstd, be = beta[c];
        float4 v = src[i];
        v.x = (v.x - mu)*ga + be;
        v.y = (v.y - mu)*ga + be;
        v.z = (v.z - mu)*ga + be;
        v.w = (v.w - mu)*ga + be;
        dst[i] = v;
    }
}

// ============================ row softmax over m ============================
__global__ __launch_bounds__(256) void softmax_kernel() {
    size_t row = blockIdx.x;            // b*HW + n
    float4* p = (float4*)(g_s + row*(size_t)HW);
    float4 v = p[threadIdx.x];

    __shared__ float sh[8];
    int lane = threadIdx.x & 31, wid = threadIdx.x >> 5;

    float m = fmaxf(fmaxf(v.x, v.y), fmaxf(v.z, v.w));
    #pragma unroll
    for (int o = 16; o > 0; o >>= 1) m = fmaxf(m, __shfl_xor_sync(0xffffffffu, m, o));
    if (lane == 0) sh[wid] = m;
    __syncthreads();
    m = sh[0];
    #pragma unroll
    for (int i = 1; i < 8; i++) m = fmaxf(m, sh[i]);
    __syncthreads();

    float4 e;
    e.x = __expf(v.x - m); e.y = __expf(v.y - m);
    e.z = __expf(v.z - m); e.w = __expf(v.w - m);
    float s = e.x + e.y + e.z + e.w;
    #pragma unroll
    for (int o = 16; o > 0; o >>= 1) s += __shfl_xor_sync(0xffffffffu, s, o);
    if (lane == 0) sh[wid] = s;
    __syncthreads();
    s = sh[0];
    #pragma unroll
    for (int i = 1; i < 8; i++) s += sh[i];
    float r = 1.f / s;
    e.x *= r; e.y *= r; e.z *= r; e.w *= r;
    p[threadIdx.x] = e;
}

// ============================ tf32 tensor-core GEMM ============================
// C[b][m][n] = sum_k Aop[k][m] * Bop[k][n]  (+bias[m]) (*scale) (+res)
// AKM: A stored A[k*lda + m] else A[m*lda + k]
// BKN: B stored B[k*ldb + n] else B[n*ldb + k]
// Block tile 128x128x32, 8 warps (4 along M x 2 along N), warp tile 32x64.
// smem layout: word index = k*128 + (col ^ f(k)); f makes both scatter stores
// and fragment loads bank-conflict-free.

__device__ __forceinline__ unsigned f2tf(float x) {
    unsigned r; asm("cvt.rna.tf32.f32 %0, %1;" : "=r"(r) : "f"(x)); return r;
}
__device__ __forceinline__ int fkx(int k) {
    return ((k & 3) << 3) ^ (((k >> 2) & 7) << 2);
}

template<bool AKM, bool BKN, bool BIAS, bool RES, bool SCALE>
__global__ __launch_bounds__(256, 2) void mm_tf32(
    const float* __restrict__ Ag, const float* __restrict__ Bg,
    float* __restrict__ Cg, const float* __restrict__ bias,
    const float* __restrict__ resg,
    int N, int K, int lda, int ldb,
    long sA, long sB, long sC)
{
    __shared__ unsigned As[32*128], Bs[32*128];
    const int t = threadIdx.x, lane = t & 31, w = t >> 5;
    const int m0 = blockIdx.y * 128, n0 = blockIdx.x * 128, b = blockIdx.z;
    const float* A = Ag + (size_t)b * sA;
    const float* B = Bg + (size_t)b * sB;
    float* Cb = Cg + (size_t)b * sC;

    const int wm = (w & 3) * 32, wn = (w >> 2) * 64;
    float acc[2][8][4];
    #pragma unroll
    for (int i = 0; i < 2; i++)
        #pragma unroll
        for (int j = 0; j < 8; j++)
            #pragma unroll
            for (int r = 0; r < 4; r++) acc[i][j][r] = 0.f;

    for (int k0 = 0; k0 < K; k0 += 32) {
        // ---- stage A tile (32k x 128m) ----
        if (AKM) {
            int kk = t >> 5, m4 = (t & 31) * 4;
            #pragma unroll
            for (int p = 0; p < 4; p++) {
                int k = kk + p * 8;
                float4 v = *(const float4*)(A + (size_t)(k0 + k) * lda + m0 + m4);
                uint4 u = {f2tf(v.x), f2tf(v.y), f2tf(v.z), f2tf(v.w)};
                *(uint4*)&As[k * 128 + (m4 ^ fkx(k))] = u;
            }
        } else {
            int mr = t >> 3, kq = (t & 7) * 4;
            #pragma unroll
            for (int p = 0; p < 4; p++) {
                int m = mr + p * 32;
                float4 v = *(const float4*)(A + (size_t)(m0 + m) * lda + k0 + kq);
                As[(kq + 0) * 128 + (m ^ fkx(kq + 0))] = f2tf(v.x);
                As[(kq + 1) * 128 + (m ^ fkx(kq + 1))] = f2tf(v.y);
                As[(kq + 2) * 128 + (m ^ fkx(kq + 2))] = f2tf(v.z);
                As[(kq + 3) * 128 + (m ^ fkx(kq + 3))] = f2tf(v.w);
            }
        }
        // ---- stage B tile (32k x 128n) ----
        if (BKN) {
            int kk = t >> 5, n4 = (t & 31) * 4;
            #pragma unroll
            for (int p = 0; p < 4; p++) {
                int k = kk + p * 8;
                float4 v = *(const float4*)(B + (size_t)(k0 + k) * ldb + n0 + n4);
                uint4 u = {f2tf(v.x), f2tf(v.y), f2tf(v.z), f2tf(v.w)};
                *(uint4*)&Bs[k * 128 + (n4 ^ fkx(k))] = u;
            }
        } else {
            int nr = t >> 3, kq = (t & 7) * 4;
            #pragma unroll
            for (int p = 0; p < 4; p++) {
                int n = nr + p * 32;
                float4 v = *(const float4*)(B + (size_t)(n0 + n) * ldb + k0 + kq);
                Bs[(kq + 0) * 128 + (n ^ fkx(kq + 0))] = f2tf(v.x);
                Bs[(kq + 1) * 128 + (n ^ fkx(kq + 1))] = f2tf(v.y);
                Bs[(kq + 2) * 128 + (n ^ fkx(kq + 2))] = f2tf(v.z);
                Bs[(kq + 3) * 128 + (n ^ fkx(kq + 3))] = f2tf(v.w);
            }
        }
        __syncthreads();

        #pragma unroll
        for (int ks = 0; ks < 4; ks++) {
            const int kb = ks * 8;
            const int kk = lane & 3, gg = lane >> 2;
            const int kA0 = kb + kk, kA1 = kb + kk + 4;
            const int f0 = fkx(kA0), f1 = fkx(kA1);
            unsigned a[2][4];
            #pragma unroll
            for (int mi = 0; mi < 2; mi++) {
                int mr = wm + mi * 16 + gg;
                a[mi][0] = As[kA0 * 128 + (mr ^ f0)];
                a[mi][1] = As[kA0 * 128 + ((mr + 8) ^ f0)];
                a[mi][2] = As[kA1 * 128 + (mr ^ f1)];
                a[mi][3] = As[kA1 * 128 + ((mr + 8) ^ f1)];
            }
            unsigned bb[8][2];
            #pragma unroll
            for (int ni = 0; ni < 8; ni++) {
                int nc = wn + ni * 8 + gg;
                bb[ni][0] = Bs[kA0 * 128 + (nc ^ f0)];
                bb[ni][1] = Bs[kA1 * 128 + (nc ^ f1)];
            }
            #pragma unroll
            for (int mi = 0; mi < 2; mi++)
                #pragma unroll
                for (int ni = 0; ni < 8; ni++)
                    asm volatile(
                        "mma.sync.aligned.m16n8k8.row.col.f32.tf32.tf32.f32 "
                        "{%0,%1,%2,%3}, {%4,%5,%6,%7}, {%8,%9}, {%0,%1,%2,%3};"
                        : "+f"(acc[mi][ni][0]), "+f"(acc[mi][ni][1]),
                          "+f"(acc[mi][ni][2]), "+f"(acc[mi][ni][3])
                        : "r"(a[mi][0]), "r"(a[mi][1]), "r"(a[mi][2]), "r"(a[mi][3]),
                          "r"(bb[ni][0]), "r"(bb[ni][1]));
        }
        __syncthreads();
    }

    // ---- epilogue ----
    #pragma unroll
    for (int mi = 0; mi < 2; mi++) {
        int r0 = m0 + wm + mi * 16 + (lane >> 2);
        float b0v = 0.f, b1v = 0.f;
        if (BIAS) { b0v = bias[r0]; b1v = bias[r0 + 8]; }
        #pragma unroll
        for (int ni = 0; ni < 8; ni++) {
            int cc = n0 + wn + ni * 8 + (lane & 3) * 2;
            float v0 = acc[mi][ni][0], v1 = acc[mi][ni][1];
            float v2 = acc[mi][ni][2], v3 = acc[mi][ni][3];
            if (SCALE) { v0 *= QK_SCALE; v1 *= QK_SCALE; v2 *= QK_SCALE; v3 *= QK_SCALE; }
            v0 += b0v; v1 += b0v; v2 += b1v; v3 += b1v;
            if (RES) {
                float2 ra = *(const float2*)(resg + (size_t)b * sC + (size_t)r0 * N + cc);
                float2 rb = *(const float2*)(resg + (size_t)b * sC + (size_t)(r0 + 8) * N + cc);
                v0 += ra.x; v1 += ra.y; v2 += rb.x; v3 += rb.y;
            }
            float2 o0 = {v0, v1}, o1 = {v2, v3};
            *(float2*)(Cb + (size_t)r0 * N + cc) = o0;
            *(float2*)(Cb + (size_t)(r0 + 8) * N + cc) = o1;
        }
    }
}

// ============================ launch ============================
extern "C" void kernel_launch(void* const* d_in, const int* in_sizes, int n_in,
                              void* d_out, int out_size) {
    const float* inp   = (const float*)d_in[0];
    const float* gamma = (const float*)d_in[1];
    const float* beta  = (const float*)d_in[2];
    const float* Wq    = (const float*)d_in[3];
    const float* bq    = (const float*)d_in[4];
    const float* Wk    = (const float*)d_in[5];
    const float* bk    = (const float*)d_in[6];
    const float* Wv    = (const float*)d_in[7];
    const float* bv    = (const float*)d_in[8];
    const float* Wo    = (const float*)d_in[9];
    const float* bo    = (const float*)d_in[10];
    float* out = (float*)d_out;

    void *px, *pq, *pk, *pv, *ps, *pa;
    cudaGetSymbolAddress(&px, g_x);
    cudaGetSymbolAddress(&pq, g_q);
    cudaGetSymbolAddress(&pk, g_k);
    cudaGetSymbolAddress(&pv, g_v);
    cudaGetSymbolAddress(&ps, g_s);
    cudaGetSymbolAddress(&pa, g_a);

    const long sCH = (long)C * HW;
    const long sHH = (long)HW * HW;

    gn_kernel<<<BATCH*NGROUP, 256>>>(inp, gamma, beta);

    // Q/K/V = W @ x + b   (A = weight (M,K) row-major, B = x (K,N))
    mm_tf32<false, true, true, false, false><<<dim3(HW/128, C/128, BATCH), 256>>>(
        Wq, (const float*)px, (float*)pq, bq, nullptr, HW, C, C, HW, 0, sCH, sCH);
    mm_tf32<false, true, true, false, false><<<dim3(HW/128, C/128, BATCH), 256>>>(
        Wk, (const float*)px, (float*)pk, bk, nullptr, HW, C, C, HW, 0, sCH, sCH);
    mm_tf32<false, true, true, false, false><<<dim3(HW/128, C/128, BATCH), 256>>>(
        Wv, (const float*)px, (float*)pv, bv, nullptr, HW, C, C, HW, 0, sCH, sCH);

    // S[n][m] = scale * sum_c Q[c][n] K[c][m]   (A = Q (K,M), B = K (K,N))
    mm_tf32<true, true, false, false, true><<<dim3(HW/128, HW/128, BATCH), 256>>>(
        (const float*)pq, (const float*)pk, (float*)ps, nullptr, nullptr,
        HW, C, HW, HW, sCH, sCH, sHH);

    softmax_kernel<<<BATCH*HW, 256>>>();

    // A[c][n] = sum_m V[c][m] attn[n][m]   (A = V (M,K), B = attn (N,K))
    mm_tf32<false, false, false, false, false><<<dim3(HW/128, C/128, BATCH), 256>>>(
        (const float*)pv, (const float*)ps, (float*)pa, nullptr, nullptr,
        HW, HW, HW, HW, sCH, sHH, sCH);

    // out = Wo @ A + bo + inp
    mm_tf32<false, true, true, true, false><<<dim3(HW/128, C/128, BATCH), 256>>>(
        Wo, (const float*)pa, out, bo, inp, HW, C, C, HW, 0, sCH, sCH);
}

// round 4
// speedup vs baseline: 3.9086x; 1.7645x over previous
#include <cuda_runtime.h>
#include <math.h>
#include <stdint.h>

#define BATCH 16
#define C 512
#define HW 1024
#define NGROUP 32
#define CPG 16
#define GSIZE (CPG*HW)
#define QK_SCALE 0.04419417382415922f  // 1/sqrt(512)

// -------- scratch (static device globals; no runtime allocation) --------
__device__ float g_xt[BATCH*HW*C];  // normalized input, transposed [b][n][c]
__device__ float g_q[BATCH*HW*C];   // Q_t [b][n][c]
__device__ float g_k[BATCH*HW*C];   // K_t [b][m][c]
__device__ float g_v[BATCH*C*HW];   // V   [b][c][m]
__device__ float g_s[BATCH*HW*HW];  // attn [b][n][m]
__device__ float g_a[BATCH*HW*C];   // A_t [b][n][c]

// ============================ GroupNorm (transposed output) ============================
// One block per (batch, group). Group = 16 channels * 1024 px contiguous in inp.
// Writes x_t[b][n][g*16..g*16+16) -- 64B contiguous chunks per n.
__global__ __launch_bounds__(256) void gn_kernel(const float* __restrict__ inp,
                                                 const float* __restrict__ gamma,
                                                 const float* __restrict__ beta) {
    int bg = blockIdx.x;
    int b = bg / NGROUP, g = bg % NGROUP;
    const float* src = inp + (size_t)bg * GSIZE;

    float s = 0.f, ss = 0.f;
    const float4* src4 = (const float4*)src;
    #pragma unroll 4
    for (int i = threadIdx.x; i < GSIZE/4; i += 256) {
        float4 v = src4[i];
        s  += v.x + v.y + v.z + v.w;
        ss += v.x*v.x + v.y*v.y + v.z*v.z + v.w*v.w;
    }
    __shared__ float sh1[8], sh2[8];
    #pragma unroll
    for (int o = 16; o > 0; o >>= 1) {
        s  += __shfl_down_sync(0xffffffffu, s,  o);
        ss += __shfl_down_sync(0xffffffffu, ss, o);
    }
    int lane = threadIdx.x & 31, wid = threadIdx.x >> 5;
    if (lane == 0) { sh1[wid] = s; sh2[wid] = ss; }
    __syncthreads();
    if (threadIdx.x == 0) {
        float t1 = 0.f, t2 = 0.f;
        #pragma unroll
        for (int i = 0; i < 8; i++) { t1 += sh1[i]; t2 += sh2[i]; }
        sh1[0] = t1; sh2[0] = t2;
    }
    __syncthreads();
    float mu   = sh1[0] * (1.f/GSIZE);
    float var  = sh2[0] * (1.f/GSIZE) - mu*mu;
    float rstd = rsqrtf(var + 1e-6f);

    float ga[CPG], be[CPG];
    #pragma unroll
    for (int c = 0; c < CPG; c++) {
        ga[c] = gamma[g*CPG + c] * rstd;
        be[c] = beta[g*CPG + c];
    }

    float* dst = g_xt + (size_t)b*HW*C + g*CPG;
    #pragma unroll
    for (int p = 0; p < 4; p++) {
        int n = threadIdx.x + p*256;
        float o[CPG];
        #pragma unroll
        for (int c = 0; c < CPG; c++)
            o[c] = (src[c*HW + n] - mu) * ga[c] + be[c];   // coalesced across lanes
        float* d = dst + (size_t)n * C;
        #pragma unroll
        for (int q = 0; q < 4; q++) {
            float4 v = {o[q*4+0], o[q*4+1], o[q*4+2], o[q*4+3]};
            *(float4*)(d + q*4) = v;
        }
    }
}

// ============================ row softmax over m ============================
__global__ __launch_bounds__(256) void softmax_kernel() {
    size_t row = blockIdx.x;            // b*HW + n
    float4* p = (float4*)(g_s + row*(size_t)HW);
    float4 v = p[threadIdx.x];

    __shared__ float sh[8];
    int lane = threadIdx.x & 31, wid = threadIdx.x >> 5;

    float m = fmaxf(fmaxf(v.x, v.y), fmaxf(v.z, v.w));
    #pragma unroll
    for (int o = 16; o > 0; o >>= 1) m = fmaxf(m, __shfl_xor_sync(0xffffffffu, m, o));
    if (lane == 0) sh[wid] = m;
    __syncthreads();
    m = sh[0];
    #pragma unroll
    for (int i = 1; i < 8; i++) m = fmaxf(m, sh[i]);
    __syncthreads();

    float4 e;
    e.x = __expf(v.x - m); e.y = __expf(v.y - m);
    e.z = __expf(v.z - m); e.w = __expf(v.w - m);
    float s = e.x + e.y + e.z + e.w;
    #pragma unroll
    for (int o = 16; o > 0; o >>= 1) s += __shfl_xor_sync(0xffffffffu, s, o);
    if (lane == 0) sh[wid] = s;
    __syncthreads();
    s = sh[0];
    #pragma unroll
    for (int i = 1; i < 8; i++) s += sh[i];
    float r = 1.f / s;
    e.x *= r; e.y *= r; e.z *= r; e.w *= r;
    p[threadIdx.x] = e;
}

// ============================ unified TN tf32 GEMM ============================
// C[b][m][n] = sum_k A[m][k] * B[n][k]   (both operands k-contiguous)
// (+bias[m] if BROW) (+bias[n] if BCOL) (*QK_SCALE if SCALE) (+res if RES)
// 128x128x32 block tile, 8 warps (4M x 2N), warp tile 32x64.
// cp.async double-buffered staging; ldmatrix.x4 fragment loads.
// smem tile layout: 16B unit u = row*8 + (kgroup ^ (row&7))  -- conflict-free
// for both cp.async stores and ldmatrix reads.

#define STAGE_BYTES 32768   // A(16KB) + B(16KB) per stage

__device__ __forceinline__ void cp16(uint32_t saddr, const float* g) {
    asm volatile("cp.async.cg.shared.global [%0], [%1], 16;" :: "r"(saddr), "l"(g));
}
#define LDSM4(R0,R1,R2,R3,ADDR) \
    asm volatile("ldmatrix.sync.aligned.m8n8.x4.shared.b16 {%0,%1,%2,%3}, [%4];" \
        : "=r"(R0), "=r"(R1), "=r"(R2), "=r"(R3) : "r"(ADDR))

template<bool BROW, bool BCOL, bool RES, bool SCALE>
__global__ __launch_bounds__(256, 2) void gemm_tn(
    const float* __restrict__ Ag, const float* __restrict__ Bg,
    float* __restrict__ Cg, const float* __restrict__ bias,
    const float* __restrict__ resg,
    int N, int K, int lda, int ldb,
    long sA, long sB, long sC)
{
    extern __shared__ float smem[];
    const uint32_t smem_u32 = (uint32_t)__cvta_generic_to_shared(smem);

    const int t = threadIdx.x, lane = t & 31, w = t >> 5;
    const int m0 = blockIdx.y * 128, n0 = blockIdx.x * 128, b = blockIdx.z;
    const float* Ab = Ag + (size_t)b * sA + (size_t)m0 * lda;
    const float* Bb = Bg + (size_t)b * sB + (size_t)n0 * ldb;
    float* Cb = Cg + (size_t)b * sC;

    // ---- staging offsets (4 x 16B per operand per thread) ----
    uint32_t soff[4]; uint32_t gAo[4], gBo[4];
    #pragma unroll
    for (int p = 0; p < 4; p++) {
        int idx = t + 256*p;
        int row = idx >> 3, gc = idx & 7;
        soff[p] = (uint32_t)((row*8 + (gc ^ (row & 7))) * 16);
        gAo[p] = (uint32_t)(row * lda + gc*4);
        gBo[p] = (uint32_t)(row * ldb + gc*4);
    }

    // ---- fragment smem address precompute ----
    const int wm = (w & 3) * 32, wn = (w >> 2) * 64;
    int amrow[2], am7[2];
    #pragma unroll
    for (int mi = 0; mi < 2; mi++) {
        int m = wm + mi*16 + (lane & 7) + ((lane & 8) ? 8 : 0);
        amrow[mi] = m * 8; am7[mi] = m & 7;
    }
    const int kgA = (lane & 16) ? 1 : 0;
    int bnrow[4], bn7[4];
    #pragma unroll
    for (int P = 0; P < 4; P++) {
        int n = wn + P*16 + (lane & 7) + ((lane & 16) ? 8 : 0);
        bnrow[P] = n * 8; bn7[P] = n & 7;
    }
    const int kgB = (lane & 8) ? 1 : 0;

    float acc[2][8][4];
    #pragma unroll
    for (int i = 0; i < 2; i++)
        #pragma unroll
        for (int j = 0; j < 8; j++)
            #pragma unroll
            for (int r = 0; r < 4; r++) acc[i][j][r] = 0.f;

    const int NTILES = K >> 5;

    // prologue: stage 0
    {
        uint32_t sa = smem_u32, sb = smem_u32 + 16384;
        #pragma unroll
        for (int p = 0; p < 4; p++) cp16(sa + soff[p], Ab + gAo[p]);
        #pragma unroll
        for (int p = 0; p < 4; p++) cp16(sb + soff[p], Bb + gBo[p]);
        asm volatile("cp.async.commit_group;" ::: "memory");
    }

    for (int kt = 0; kt < NTILES; kt++) {
        if (kt + 1 < NTILES) {
            int st = (kt + 1) & 1, k0 = (kt + 1) << 5;
            uint32_t sa = smem_u32 + st*STAGE_BYTES, sb = sa + 16384;
            #pragma unroll
            for (int p = 0; p < 4; p++) cp16(sa + soff[p], Ab + gAo[p] + k0);
            #pragma unroll
            for (int p = 0; p < 4; p++) cp16(sb + soff[p], Bb + gBo[p] + k0);
            asm volatile("cp.async.commit_group;" ::: "memory");
            asm volatile("cp.async.wait_group 1;" ::: "memory");
        } else {
            asm volatile("cp.async.wait_group 0;" ::: "memory");
        }
        __syncthreads();

        const uint32_t sa = smem_u32 + (kt & 1)*STAGE_BYTES;
        const uint32_t sb = sa + 16384;
        #pragma unroll
        for (int ks = 0; ks < 4; ks++) {
            unsigned a[2][4];
            #pragma unroll
            for (int mi = 0; mi < 2; mi++) {
                uint32_t ad = sa + (uint32_t)((amrow[mi] + ((2*ks + kgA) ^ am7[mi])) * 16);
                LDSM4(a[mi][0], a[mi][1], a[mi][2], a[mi][3], ad);
            }
            unsigned bf[8][2];
            #pragma unroll
            for (int P = 0; P < 4; P++) {
                uint32_t bd = sb + (uint32_t)((bnrow[P] + ((2*ks + kgB) ^ bn7[P])) * 16);
                LDSM4(bf[2*P][0], bf[2*P][1], bf[2*P+1][0], bf[2*P+1][1], bd);
            }
            #pragma unroll
            for (int mi = 0; mi < 2; mi++)
                #pragma unroll
                for (int ni = 0; ni < 8; ni++)
                    asm volatile(
                        "mma.sync.aligned.m16n8k8.row.col.f32.tf32.tf32.f32 "
                        "{%0,%1,%2,%3}, {%4,%5,%6,%7}, {%8,%9}, {%0,%1,%2,%3};"
                        : "+f"(acc[mi][ni][0]), "+f"(acc[mi][ni][1]),
                          "+f"(acc[mi][ni][2]), "+f"(acc[mi][ni][3])
                        : "r"(a[mi][0]), "r"(a[mi][1]), "r"(a[mi][2]), "r"(a[mi][3]),
                          "r"(bf[ni][0]), "r"(bf[ni][1]));
        }
        __syncthreads();
    }

    // ---- epilogue ----
    #pragma unroll
    for (int mi = 0; mi < 2; mi++) {
        int r0 = m0 + wm + mi*16 + (lane >> 2);
        float br0 = 0.f, br1 = 0.f;
        if (BROW) { br0 = bias[r0]; br1 = bias[r0 + 8]; }
        #pragma unroll
        for (int ni = 0; ni < 8; ni++) {
            int cc = n0 + wn + ni*8 + (lane & 3)*2;
            float v0 = acc[mi][ni][0], v1 = acc[mi][ni][1];
            float v2 = acc[mi][ni][2], v3 = acc[mi][ni][3];
            if (SCALE) { v0 *= QK_SCALE; v1 *= QK_SCALE; v2 *= QK_SCALE; v3 *= QK_SCALE; }
            if (BROW) { v0 += br0; v1 += br0; v2 += br1; v3 += br1; }
            if (BCOL) {
                float bc0 = bias[cc], bc1 = bias[cc + 1];
                v0 += bc0; v1 += bc1; v2 += bc0; v3 += bc1;
            }
            if (RES) {
                float2 ra = *(const float2*)(resg + (size_t)b*sC + (size_t)r0*N + cc);
                float2 rb = *(const float2*)(resg + (size_t)b*sC + (size_t)(r0+8)*N + cc);
                v0 += ra.x; v1 += ra.y; v2 += rb.x; v3 += rb.y;
            }
            float2 o0 = {v0, v1}, o1 = {v2, v3};
            *(float2*)(Cb + (size_t)r0*N + cc) = o0;
            *(float2*)(Cb + (size_t)(r0+8)*N + cc) = o1;
        }
    }
}

// ============================ launch ============================
extern "C" void kernel_launch(void* const* d_in, const int* in_sizes, int n_in,
                              void* d_out, int out_size) {
    const float* inp   = (const float*)d_in[0];
    const float* gamma = (const float*)d_in[1];
    const float* beta  = (const float*)d_in[2];
    const float* Wq    = (const float*)d_in[3];
    const float* bq    = (const float*)d_in[4];
    const float* Wk    = (const float*)d_in[5];
    const float* bk    = (const float*)d_in[6];
    const float* Wv    = (const float*)d_in[7];
    const float* bv    = (const float*)d_in[8];
    const float* Wo    = (const float*)d_in[9];
    const float* bo    = (const float*)d_in[10];
    float* out = (float*)d_out;

    void *pxt, *pq, *pk, *pv, *ps, *pa;
    cudaGetSymbolAddress(&pxt, g_xt);
    cudaGetSymbolAddress(&pq, g_q);
    cudaGetSymbolAddress(&pk, g_k);
    cudaGetSymbolAddress(&pv, g_v);
    cudaGetSymbolAddress(&ps, g_s);
    cudaGetSymbolAddress(&pa, g_a);

    const long sNC = (long)HW * C;   // 1024*512
    const long sHH = (long)HW * HW;
    const int SMEM = 2 * STAGE_BYTES;

    cudaFuncSetAttribute(gemm_tn<false,true,false,false>, cudaFuncAttributeMaxDynamicSharedMemorySize, SMEM);
    cudaFuncSetAttribute(gemm_tn<true,false,false,false>, cudaFuncAttributeMaxDynamicSharedMemorySize, SMEM);
    cudaFuncSetAttribute(gemm_tn<false,false,false,true>, cudaFuncAttributeMaxDynamicSharedMemorySize, SMEM);
    cudaFuncSetAttribute(gemm_tn<false,false,false,false>, cudaFuncAttributeMaxDynamicSharedMemorySize, SMEM);
    cudaFuncSetAttribute(gemm_tn<true,false,true,false>, cudaFuncAttributeMaxDynamicSharedMemorySize, SMEM);

    gn_kernel<<<BATCH*NGROUP, 256>>>(inp, gamma, beta);

    // Q_t[n][o] = sum_c x_t[n][c] Wq[o][c] + bq[o]   (M=n=1024, N=o=512)
    gemm_tn<false,true,false,false><<<dim3(C/128, HW/128, BATCH), 256, SMEM>>>(
        (const float*)pxt, Wq, (float*)pq, bq, nullptr, C, C, C, C, sNC, 0, sNC);
    // K_t[m][o]
    gemm_tn<false,true,false,false><<<dim3(C/128, HW/128, BATCH), 256, SMEM>>>(
        (const float*)pxt, Wk, (float*)pk, bk, nullptr, C, C, C, C, sNC, 0, sNC);
    // V[c][m] = sum_c' Wv[c][c'] x_t[m][c'] + bv[c]  (M=c=512, N=m=1024)
    gemm_tn<true,false,false,false><<<dim3(HW/128, C/128, BATCH), 256, SMEM>>>(
        Wv, (const float*)pxt, (float*)pv, bv, nullptr, HW, C, C, C, 0, sNC, sNC);

    // S[n][m] = scale * sum_c Q_t[n][c] K_t[m][c]   (M=n=1024, N=m=1024, K=512)
    gemm_tn<false,false,false,true><<<dim3(HW/128, HW/128, BATCH), 256, SMEM>>>(
        (const float*)pq, (const float*)pk, (float*)ps, nullptr, nullptr,
        HW, C, C, C, sNC, sNC, sHH);

    softmax_kernel<<<BATCH*HW, 256>>>();

    // A_t[n][c] = sum_m attn[n][m] V[c][m]   (M=n=1024, N=c=512, K=1024)
    gemm_tn<false,false,false,false><<<dim3(C/128, HW/128, BATCH), 256, SMEM>>>(
        (const float*)ps, (const float*)pv, (float*)pa, nullptr, nullptr,
        C, HW, HW, HW, sHH, sNC, sNC);

    // out[o][n] = sum_c Wo[o][c] A_t[n][c] + bo[o] + inp[o][n]  (M=o=512, N=n=1024)
    gemm_tn<true,false,true,false><<<dim3(HW/128, C/128, BATCH), 256, SMEM>>>(
        Wo, (const float*)pa, out, bo, inp, HW, C, C, C, 0, sNC, sNC);
}

// round 6
// speedup vs baseline: 4.0137x; 1.0269x over previous
#include <cuda_runtime.h>
#include <math.h>
#include <stdint.h>

#define BATCH 16
#define C 512
#define HW 1024
#define NGROUP 32
#define CPG 16
#define GSIZE (CPG*HW)
#define QK_SCALE 0.04419417382415922f  // 1/sqrt(512)

// -------- scratch (static device globals; no runtime allocation) --------
__device__ float g_xt[BATCH*HW*C];  // normalized input, transposed [b][n][c]
__device__ float g_q[BATCH*HW*C];   // Q_t [b][n][c]
__device__ float g_k[BATCH*HW*C];   // K_t [b][m][c]
__device__ float g_v[BATCH*C*HW];   // V   [b][c][m]
__device__ float g_s[BATCH*HW*HW];  // attn [b][n][m]
__device__ float g_a[BATCH*HW*C];   // A_t [b][n][c]

// ============================ GroupNorm (transposed output) ============================
__global__ __launch_bounds__(256) void gn_kernel(const float* __restrict__ inp,
                                                 const float* __restrict__ gamma,
                                                 const float* __restrict__ beta) {
    int bg = blockIdx.x;
    int b = bg / NGROUP, g = bg % NGROUP;
    const float* src = inp + (size_t)bg * GSIZE;

    float s = 0.f, ss = 0.f;
    const float4* src4 = (const float4*)src;
    #pragma unroll 4
    for (int i = threadIdx.x; i < GSIZE/4; i += 256) {
        float4 v = src4[i];
        s  += v.x + v.y + v.z + v.w;
        ss += v.x*v.x + v.y*v.y + v.z*v.z + v.w*v.w;
    }
    __shared__ float sh1[8], sh2[8];
    #pragma unroll
    for (int o = 16; o > 0; o >>= 1) {
        s  += __shfl_down_sync(0xffffffffu, s,  o);
        ss += __shfl_down_sync(0xffffffffu, ss, o);
    }
    int lane = threadIdx.x & 31, wid = threadIdx.x >> 5;
    if (lane == 0) { sh1[wid] = s; sh2[wid] = ss; }
    __syncthreads();
    if (threadIdx.x == 0) {
        float t1 = 0.f, t2 = 0.f;
        #pragma unroll
        for (int i = 0; i < 8; i++) { t1 += sh1[i]; t2 += sh2[i]; }
        sh1[0] = t1; sh2[0] = t2;
    }
    __syncthreads();
    float mu   = sh1[0] * (1.f/GSIZE);
    float var  = sh2[0] * (1.f/GSIZE) - mu*mu;
    float rstd = rsqrtf(var + 1e-6f);

    float ga[CPG], be[CPG];
    #pragma unroll
    for (int c = 0; c < CPG; c++) {
        ga[c] = gamma[g*CPG + c] * rstd;
        be[c] = beta[g*CPG + c];
    }

    float* dst = g_xt + (size_t)b*HW*C + g*CPG;
    #pragma unroll
    for (int p = 0; p < 4; p++) {
        int n = threadIdx.x + p*256;
        float o[CPG];
        #pragma unroll
        for (int c = 0; c < CPG; c++)
            o[c] = (src[c*HW + n] - mu) * ga[c] + be[c];
        float* d = dst + (size_t)n * C;
        #pragma unroll
        for (int q = 0; q < 4; q++) {
            float4 v = {o[q*4+0], o[q*4+1], o[q*4+2], o[q*4+3]};
            *(float4*)(d + q*4) = v;
        }
    }
}

// ============================ row softmax over m (2 rows/block) ============================
__global__ __launch_bounds__(256) void softmax_kernel() {
    const int half = threadIdx.x >> 7;       // 0/1 -> row within block
    const int t = threadIdx.x & 127;
    const size_t row = (size_t)blockIdx.x * 2 + half;
    float4* p = (float4*)(g_s + row * (size_t)HW);
    float4 v0 = p[t], v1 = p[t + 128];       // 2 independent loads (MLP=2/thread)

    __shared__ float sh[2][4];
    const int lane = threadIdx.x & 31;
    const int wloc = (threadIdx.x >> 5) & 3; // warp index within half

    float m = fmaxf(fmaxf(fmaxf(v0.x, v0.y), fmaxf(v0.z, v0.w)),
                    fmaxf(fmaxf(v1.x, v1.y), fmaxf(v1.z, v1.w)));
    #pragma unroll
    for (int o = 16; o > 0; o >>= 1) m = fmaxf(m, __shfl_xor_sync(0xffffffffu, m, o));
    if (lane == 0) sh[half][wloc] = m;
    __syncthreads();
    m = fmaxf(fmaxf(sh[half][0], sh[half][1]), fmaxf(sh[half][2], sh[half][3]));
    __syncthreads();

    float4 e0, e1;
    e0.x = __expf(v0.x - m); e0.y = __expf(v0.y - m);
    e0.z = __expf(v0.z - m); e0.w = __expf(v0.w - m);
    e1.x = __expf(v1.x - m); e1.y = __expf(v1.y - m);
    e1.z = __expf(v1.z - m); e1.w = __expf(v1.w - m);
    float s = e0.x + e0.y + e0.z + e0.w + e1.x + e1.y + e1.z + e1.w;
    #pragma unroll
    for (int o = 16; o > 0; o >>= 1) s += __shfl_xor_sync(0xffffffffu, s, o);
    if (lane == 0) sh[half][wloc] = s;
    __syncthreads();
    s = sh[half][0] + sh[half][1] + sh[half][2] + sh[half][3];
    float r = 1.f / s;
    e0.x *= r; e0.y *= r; e0.z *= r; e0.w *= r;
    e1.x *= r; e1.y *= r; e1.z *= r; e1.w *= r;
    p[t] = e0;
    p[t + 128] = e1;
}

// ============================ unified TN tf32 GEMM ============================
// C[b][m][n] = sum_k A[m][k] * B[n][k]   (both operands k-contiguous)
// 128x128x32 block tile, 8 warps (4M x 2N), warp tile 32x64.
// 3-stage cp.async pipeline, ONE __syncthreads per k-tile.
// smem 16B-unit layout: u = row*8 + (kgroup ^ (row&7))  (SW128-style, conflict-free
// for both cp.async stores and ldmatrix reads).

#define STAGE_BYTES 32768   // A(16KB) + B(16KB) per stage
#define NSTAGE 3
#define SMEM_TOT (NSTAGE*STAGE_BYTES)

__device__ __forceinline__ void cp16(uint32_t saddr, const float* g) {
    asm volatile("cp.async.cg.shared.global [%0], [%1], 16;" :: "r"(saddr), "l"(g));
}
#define LDSM4(R0,R1,R2,R3,ADDR) \
    asm volatile("ldmatrix.sync.aligned.m8n8.x4.shared.b16 {%0,%1,%2,%3}, [%4];" \
        : "=r"(R0), "=r"(R1), "=r"(R2), "=r"(R3) : "r"(ADDR))

template<bool BROW, bool BCOL, bool RES, bool SCALE>
__global__ __launch_bounds__(256, 2) void gemm_tn(
    const float* __restrict__ Ag, const float* __restrict__ Bg,
    float* __restrict__ Cg, const float* __restrict__ bias,
    const float* __restrict__ resg,
    int N, int K, int lda, int ldb,
    long sA, long sB, long sC)
{
    extern __shared__ float smem[];
    const uint32_t smem_u32 = (uint32_t)__cvta_generic_to_shared(smem);

    const int t = threadIdx.x, lane = t & 31, w = t >> 5;
    const int m0 = blockIdx.y * 128, n0 = blockIdx.x * 128, b = blockIdx.z;
    const float* Ab = Ag + (size_t)b * sA + (size_t)m0 * lda;
    const float* Bb = Bg + (size_t)b * sB + (size_t)n0 * ldb;
    float* Cb = Cg + (size_t)b * sC;

    // ---- staging offsets (4 x 16B per operand per thread) ----
    uint32_t soff[4]; uint32_t gAo[4], gBo[4];
    #pragma unroll
    for (int p = 0; p < 4; p++) {
        int idx = t + 256*p;
        int row = idx >> 3, gc = idx & 7;
        soff[p] = (uint32_t)((row*8 + (gc ^ (row & 7))) * 16);
        gAo[p] = (uint32_t)(row * lda + gc*4);
        gBo[p] = (uint32_t)(row * ldb + gc*4);
    }

    // ---- fragment smem address precompute ----
    const int wm = (w & 3) * 32, wn = (w >> 2) * 64;
    int amrow[2], am7[2];
    #pragma unroll
    for (int mi = 0; mi < 2; mi++) {
        int m = wm + mi*16 + (lane & 7) + ((lane & 8) ? 8 : 0);
        amrow[mi] = m * 8; am7[mi] = m & 7;
    }
    const int kgA = (lane & 16) ? 1 : 0;
    int bnrow[4], bn7[4];
    #pragma unroll
    for (int P = 0; P < 4; P++) {
        int n = wn + P*16 + (lane & 7) + ((lane & 16) ? 8 : 0);
        bnrow[P] = n * 8; bn7[P] = n & 7;
    }
    const int kgB = (lane & 8) ? 1 : 0;

    float acc[2][8][4];
    #pragma unroll
    for (int i = 0; i < 2; i++)
        #pragma unroll
        for (int j = 0; j < 8; j++)
            #pragma unroll
            for (int r = 0; r < 4; r++) acc[i][j][r] = 0.f;

    const int NTILES = K >> 5;

    // prologue: stage tiles 0 and 1
    #pragma unroll
    for (int kt = 0; kt < 2; kt++) {
        uint32_t sa = smem_u32 + kt*STAGE_BYTES, sb = sa + 16384;
        #pragma unroll
        for (int p = 0; p < 4; p++) cp16(sa + soff[p], Ab + gAo[p] + kt*32);
        #pragma unroll
        for (int p = 0; p < 4; p++) cp16(sb + soff[p], Bb + gBo[p] + kt*32);
        asm volatile("cp.async.commit_group;" ::: "memory");
    }

    int buf = 0;              // = kt % 3
    int sbuf = 2;             // = (kt+2) % 3
    for (int kt = 0; kt < NTILES; kt++) {
        // tile kt arrived?
        if (kt + 1 < NTILES) asm volatile("cp.async.wait_group 1;" ::: "memory");
        else                 asm volatile("cp.async.wait_group 0;" ::: "memory");
        __syncthreads();      // orders compute(kt-1) before staging into sbuf

        // stage tile kt+2 into buffer (kt+2)%3 — overlaps compute(kt)
        if (kt + 2 < NTILES) {
            int k0 = (kt + 2) << 5;
            uint32_t sa = smem_u32 + sbuf*STAGE_BYTES, sb = sa + 16384;
            #pragma unroll
            for (int p = 0; p < 4; p++) cp16(sa + soff[p], Ab + gAo[p] + k0);
            #pragma unroll
            for (int p = 0; p < 4; p++) cp16(sb + soff[p], Bb + gBo[p] + k0);
            asm volatile("cp.async.commit_group;" ::: "memory");
        }

        const uint32_t sa = smem_u32 + buf*STAGE_BYTES;
        const uint32_t sb = sa + 16384;

        // A-fragment prefetch across ks
        unsigned a[2][2][4];
        #pragma unroll
        for (int mi = 0; mi < 2; mi++) {
            uint32_t ad = sa + (uint32_t)((amrow[mi] + (kgA ^ am7[mi])) * 16);
            LDSM4(a[0][mi][0], a[0][mi][1], a[0][mi][2], a[0][mi][3], ad);
        }
        #pragma unroll
        for (int ks = 0; ks < 4; ks++) {
            const int cur = ks & 1, nxt = cur ^ 1;
            if (ks < 3) {
                #pragma unroll
                for (int mi = 0; mi < 2; mi++) {
                    uint32_t ad = sa + (uint32_t)((amrow[mi] + ((2*(ks+1) + kgA) ^ am7[mi])) * 16);
                    LDSM4(a[nxt][mi][0], a[nxt][mi][1], a[nxt][mi][2], a[nxt][mi][3], ad);
                }
            }
            unsigned bf[8][2];
            #pragma unroll
            for (int P = 0; P < 4; P++) {
                uint32_t bd = sb + (uint32_t)((bnrow[P] + ((2*ks + kgB) ^ bn7[P])) * 16);
                LDSM4(bf[2*P][0], bf[2*P][1], bf[2*P+1][0], bf[2*P+1][1], bd);
            }
            #pragma unroll
            for (int mi = 0; mi < 2; mi++)
                #pragma unroll
                for (int ni = 0; ni < 8; ni++)
                    asm volatile(
                        "mma.sync.aligned.m16n8k8.row.col.f32.tf32.tf32.f32 "
                        "{%0,%1,%2,%3}, {%4,%5,%6,%7}, {%8,%9}, {%0,%1,%2,%3};"
                        : "+f"(acc[mi][ni][0]), "+f"(acc[mi][ni][1]),
                          "+f"(acc[mi][ni][2]), "+f"(acc[mi][ni][3])
                        : "r"(a[cur][mi][0]), "r"(a[cur][mi][1]),
                          "r"(a[cur][mi][2]), "r"(a[cur][mi][3]),
                          "r"(bf[ni][0]), "r"(bf[ni][1]));
        }

        buf = (buf == 2) ? 0 : buf + 1;
        sbuf = (sbuf == 2) ? 0 : sbuf + 1;
    }

    // ---- epilogue ----
    #pragma unroll
    for (int mi = 0; mi < 2; mi++) {
        int r0 = m0 + wm + mi*16 + (lane >> 2);
        float br0 = 0.f, br1 = 0.f;
        if (BROW) { br0 = bias[r0]; br1 = bias[r0 + 8]; }
        #pragma unroll
        for (int ni = 0; ni < 8; ni++) {
            int cc = n0 + wn + ni*8 + (lane & 3)*2;
            float v0 = acc[mi][ni][0], v1 = acc[mi][ni][1];
            float v2 = acc[mi][ni][2], v3 = acc[mi][ni][3];
            if (SCALE) { v0 *= QK_SCALE; v1 *= QK_SCALE; v2 *= QK_SCALE; v3 *= QK_SCALE; }
            if (BROW) { v0 += br0; v1 += br0; v2 += br1; v3 += br1; }
            if (BCOL) {
                float bc0 = bias[cc], bc1 = bias[cc + 1];
                v0 += bc0; v1 += bc1; v2 += bc0; v3 += bc1;
            }
            if (RES) {
                float2 ra = *(const float2*)(resg + (size_t)b*sC + (size_t)r0*N + cc);
                float2 rb = *(const float2*)(resg + (size_t)b*sC + (size_t)(r0+8)*N + cc);
                v0 += ra.x; v1 += ra.y; v2 += rb.x; v3 += rb.y;
            }
            float2 o0 = {v0, v1}, o1 = {v2, v3};
            *(float2*)(Cb + (size_t)r0*N + cc) = o0;
            *(float2*)(Cb + (size_t)(r0+8)*N + cc) = o1;
        }
    }
}

// ============================ launch ============================
extern "C" void kernel_launch(void* const* d_in, const int* in_sizes, int n_in,
                              void* d_out, int out_size) {
    const float* inp   = (const float*)d_in[0];
    const float* gamma = (const float*)d_in[1];
    const float* beta  = (const float*)d_in[2];
    const float* Wq    = (const float*)d_in[3];
    const float* bq    = (const float*)d_in[4];
    const float* Wk    = (const float*)d_in[5];
    const float* bk    = (const float*)d_in[6];
    const float* Wv    = (const float*)d_in[7];
    const float* bv    = (const float*)d_in[8];
    const float* Wo    = (const float*)d_in[9];
    const float* bo    = (const float*)d_in[10];
    float* out = (float*)d_out;

    void *pxt, *pq, *pk, *pv, *ps, *pa;
    cudaGetSymbolAddress(&pxt, g_xt);
    cudaGetSymbolAddress(&pq, g_q);
    cudaGetSymbolAddress(&pk, g_k);
    cudaGetSymbolAddress(&pv, g_v);
    cudaGetSymbolAddress(&ps, g_s);
    cudaGetSymbolAddress(&pa, g_a);

    const long sNC = (long)HW * C;
    const long sHH = (long)HW * HW;

    cudaFuncSetAttribute(gemm_tn<false,true,false,false>, cudaFuncAttributeMaxDynamicSharedMemorySize, SMEM_TOT);
    cudaFuncSetAttribute(gemm_tn<true,false,false,false>, cudaFuncAttributeMaxDynamicSharedMemorySize, SMEM_TOT);
    cudaFuncSetAttribute(gemm_tn<false,false,false,true>, cudaFuncAttributeMaxDynamicSharedMemorySize, SMEM_TOT);
    cudaFuncSetAttribute(gemm_tn<false,false,false,false>, cudaFuncAttributeMaxDynamicSharedMemorySize, SMEM_TOT);
    cudaFuncSetAttribute(gemm_tn<true,false,true,false>, cudaFuncAttributeMaxDynamicSharedMemorySize, SMEM_TOT);

    gn_kernel<<<BATCH*NGROUP, 256>>>(inp, gamma, beta);

    // Q_t[n][o] = sum_c x_t[n][c] Wq[o][c] + bq[o]   (M=n=1024, N=o=512)
    gemm_tn<false,true,false,false><<<dim3(C/128, HW/128, BATCH), 256, SMEM_TOT>>>(
        (const float*)pxt, Wq, (float*)pq, bq, nullptr, C, C, C, C, sNC, 0, sNC);
    gemm_tn<false,true,false,false><<<dim3(C/128, HW/128, BATCH), 256, SMEM_TOT>>>(
        (const float*)pxt, Wk, (float*)pk, bk, nullptr, C, C, C, C, sNC, 0, sNC);
    // V[c][m] = sum_c' Wv[c][c'] x_t[m][c'] + bv[c]  (M=c=512, N=m=1024)
    gemm_tn<true,false,false,false><<<dim3(HW/128, C/128, BATCH), 256, SMEM_TOT>>>(
        Wv, (const float*)pxt, (float*)pv, bv, nullptr, HW, C, C, C, 0, sNC, sNC);

    // S[n][m] = scale * sum_c Q_t[n][c] K_t[m][c]
    gemm_tn<false,false,false,true><<<dim3(HW/128, HW/128, BATCH), 256, SMEM_TOT>>>(
        (const float*)pq, (const float*)pk, (float*)ps, nullptr, nullptr,
        HW, C, C, C, sNC, sNC, sHH);

    softmax_kernel<<<BATCH*HW/2, 256>>>();

    // A_t[n][c] = sum_m attn[n][m] V[c][m]
    gemm_tn<false,false,false,false><<<dim3(C/128, HW/128, BATCH), 256, SMEM_TOT>>>(
        (const float*)ps, (const float*)pv, (float*)pa, nullptr, nullptr,
        C, HW, HW, HW, sHH, sNC, sNC);

    // out[o][n] = sum_c Wo[o][c] A_t[n][c] + bo[o] + inp[o][n]
    gemm_tn<true,false,true,false><<<dim3(HW/128, C/128, BATCH), 256, SMEM_TOT>>>(
        Wo, (const float*)pa, out, bo, inp, HW, C, C, C, 0, sNC, sNC);
}